// round 12
// baseline (speedup 1.0000x reference)
#include <cuda_runtime.h>
#include <cuda_fp16.h>
#include <cstdint>

// Flash-attention (causal) via mma.sync fp16 (f32 accum), round 10b (resubmit).
// 256 threads (8 warps), BM=128, BN=32, 2 CTAs/SM.
// Each warp owns 16 q-rows over the FULL kv tile; P is passed MMA1->MMA2
// in registers (C-fragment == A-fragment layout), so no P smem, no mid-iter
// barrier, warp-private l. Double-buffered K/V, 1 barrier/iter.
// q/k/v: [2048, 2, 16, 128] fp32 sbhd.  out: [2048, 2, 2048] fp32.

#define SSTRIDE  4096
#define SCALE    0.08838834764831845f
#define NT       256
#define QKS      72                  // Q/K row stride in u32 words
#define VPS      24                  // V row stride in u32 words

#define Q_U32 (128 * QKS)            // 9216
#define K_U32 (32 * QKS)             // 2304
#define V_U32 (128 * VPS)            // 3072
#define SMEM_U32 (Q_U32 + 2 * K_U32 + 2 * V_U32)
#define SMEM_BYTES (SMEM_U32 * 4)    // 79872

__device__ __forceinline__ void mma16(float* d, const uint32_t* a,
                                      uint32_t b0, uint32_t b1) {
    asm("mma.sync.aligned.m16n8k16.row.col.f32.f16.f16.f32 "
        "{%0,%1,%2,%3}, {%4,%5,%6,%7}, {%8,%9}, {%0,%1,%2,%3};"
        : "+f"(d[0]), "+f"(d[1]), "+f"(d[2]), "+f"(d[3])
        : "r"(a[0]), "r"(a[1]), "r"(a[2]), "r"(a[3]), "r"(b0), "r"(b1));
}
__device__ __forceinline__ uint32_t pack2(float x, float y) {
    uint32_t r;
    asm("cvt.rn.f16x2.f32 %0, %2, %1;" : "=r"(r) : "f"(x), "f"(y));
    return r;
}

__global__ __launch_bounds__(NT, 2)
void fa_rp_kernel(const float* __restrict__ Q,
                  const float* __restrict__ K,
                  const float* __restrict__ V,
                  float* __restrict__ out)
{
    extern __shared__ uint32_t su[];
    uint32_t* Qh = su;                       // [128 rows][QKS]
    uint32_t* Kh = Qh + Q_U32;               // 2 x [32 rows][QKS]
    uint32_t* Vh = Kh + 2 * K_U32;           // 2 x [128 d-rows][VPS]

    const int tid  = threadIdx.x;
    const int wid  = tid >> 5;
    const int lane = tid & 31;
    const int lr   = lane >> 2;   // 0..7
    const int lc   = lane & 3;    // 0..3

    const int qt = 15 - (int)blockIdx.x;     // heavy q-tiles first
    const int bh = (int)blockIdx.y;
    const int b  = bh >> 4;
    const int h  = bh & 15;
    const float* Qg = Q + bh * 128;
    const float* Kg = K + bh * 128;
    const float* Vg = V + bh * 128;

    const int q0       = qt * 128;
    const int wbase    = wid << 4;
    const int row_loc0 = wbase + lr;
    const int rg0      = q0 + row_loc0;
    const int rg1      = rg0 + 8;
    const int wrow_min = q0 + wbase;
    const int wrow_max = wrow_min + 15;

    // ---- Q tile -> Qh (fp16 interleaved words) ----
    {
        const int j = tid & 15;
        const int woff = ((j >> 1) << 3) + (j & 1);
        const int r0 = tid >> 4;             // 0..15
#pragma unroll
        for (int s = 0; s < 8; ++s) {
            const int r = r0 + (s << 4);
            const float* src = Qg + (size_t)(q0 + r) * SSTRIDE + (j << 3);
            float4 x = *(const float4*)(src);
            float4 y = *(const float4*)(src + 4);
            uint32_t* d = Qh + r * QKS + woff;
            d[0] = pack2(x.x, x.y);
            d[2] = pack2(x.z, x.w);
            d[4] = pack2(y.x, y.y);
            d[6] = pack2(y.z, y.w);
        }
    }

    // K staging coords: thread (kj 0..15, kn0 0..15), rows kn0 + 16s, s<2
    const int kj    = tid & 15;
    const int kn0   = tid >> 4;
    const int kwoff = ((kj >> 1) << 3) + (kj & 1);
    // V staging coords: kv pair qp = vqp0 + 8s, d block vdg (4 d's), s<2
    const int vqp0 = tid & 7;
    const int vdg  = tid >> 3;                 // 0..31
    const int vd0  = vdg << 2;
    const int vwl  = ((vqp0 & 3) << 1) + (vqp0 >> 2);   // word within 8

    uint32_t kst[2][4], vst[2][4];

#define STAGE(k0n)                                                            \
    _Pragma("unroll")                                                         \
    for (int s = 0; s < 2; ++s) {                                             \
        const int n = (k0n) + kn0 + (s << 4);                                 \
        const float* p = Kg + (size_t)n * SSTRIDE + (kj << 3);                \
        float4 x = *(const float4*)(p);                                       \
        float4 y = *(const float4*)(p + 4);                                   \
        kst[s][0] = pack2(x.x, x.y); kst[s][1] = pack2(x.z, x.w);             \
        kst[s][2] = pack2(y.x, y.y); kst[s][3] = pack2(y.z, y.w);             \
        const int qp = vqp0 + (s << 3);                                       \
        const float* pv = Vg + (size_t)((k0n) + 2 * qp) * SSTRIDE + vd0;      \
        float4 a = *(const float4*)(pv);                                      \
        float4 c = *(const float4*)(pv + SSTRIDE);                            \
        vst[s][0] = pack2(a.x, c.x); vst[s][1] = pack2(a.y, c.y);             \
        vst[s][2] = pack2(a.z, c.z); vst[s][3] = pack2(a.w, c.w);             \
    }

    // ---- prologue: stage tile 0 ----
    STAGE(0)

    float o_acc[64];
#pragma unroll
    for (int i = 0; i < 64; ++i) o_acc[i] = 0.f;
    float l0 = 0.f, l1 = 0.f;

    const int ktmax = 4 * qt + 3;
    for (int kt = 0; kt <= ktmax; ++kt) {
        const int k0 = kt << 5;
        uint32_t* Kb = Kh + (kt & 1) * K_U32;
        uint32_t* Vb = Vh + (kt & 1) * V_U32;

        // ---- commit staged tile to smem ----
#pragma unroll
        for (int s = 0; s < 2; ++s) {
            uint32_t* dk = Kb + (kn0 + (s << 4)) * QKS + kwoff;
            dk[0] = kst[s][0]; dk[2] = kst[s][1];
            dk[4] = kst[s][2]; dk[6] = kst[s][3];
            const int vw = (s << 3) + vwl;
#pragma unroll
            for (int r = 0; r < 4; ++r) {
                const int rp = (r + vdg) & 3;       // bank-spread permutation
                Vh[(kt & 1) * V_U32 + (vd0 + rp) * VPS + vw] = vst[s][rp];
            }
        }
        __syncthreads();

        // ---- prefetch next tile into registers ----
        if (kt < ktmax) { STAGE(k0 + 32) }

        const bool skip = (k0 > wrow_max);
        if (!skip) {
            // ---- MMA1: S[16, 32] = Q x K^T ----
            float sc[16];
#pragma unroll
            for (int i = 0; i < 16; ++i) sc[i] = 0.f;
#pragma unroll
            for (int ks = 0; ks < 8; ++ks) {
                const int fo = (ks << 3) + (lc << 1);
                uint2 a02 = *(const uint2*)(Qh + row_loc0 * QKS + fo);
                uint2 a13 = *(const uint2*)(Qh + (row_loc0 + 8) * QKS + fo);
                uint32_t a[4] = { a02.x, a13.x, a02.y, a13.y };
#pragma unroll
                for (int nt = 0; nt < 4; ++nt) {
                    uint2 bf = *(const uint2*)(Kb + ((nt << 3) + lr) * QKS + fo);
                    mma16(sc + 4 * nt, a, bf.x, bf.y);
                }
            }

            // ---- softmax (unnormalized) + pack P into A-fragment regs ----
            const bool diag = (k0 + 31 > wrow_min);
            uint32_t pa[2][4];
#pragma unroll
            for (int nt = 0; nt < 4; ++nt) {
                const int cg = k0 + (nt << 3) + (lc << 1);
                float p00 = __expf(sc[4 * nt + 0] * SCALE);
                float p01 = __expf(sc[4 * nt + 1] * SCALE);
                float p10 = __expf(sc[4 * nt + 2] * SCALE);
                float p11 = __expf(sc[4 * nt + 3] * SCALE);
                if (diag) {
                    if (cg     > rg0) p00 = 0.f;
                    if (cg + 1 > rg0) p01 = 0.f;
                    if (cg     > rg1) p10 = 0.f;
                    if (cg + 1 > rg1) p11 = 0.f;
                }
                l0 += p00 + p01;
                l1 += p10 + p11;
                pa[nt >> 1][((nt & 1) << 1) + 0] = pack2(p00, p01);
                pa[nt >> 1][((nt & 1) << 1) + 1] = pack2(p10, p11);
            }

            // ---- MMA2: O[16,128] += P[16,32] x V[32,128] (P from regs) ----
#pragma unroll
            for (int j = 0; j < 2; ++j) {
                const int fo = (j << 3) + (lc << 1);
#pragma unroll
                for (int nv = 0; nv < 16; ++nv) {
                    uint2 bf = *(const uint2*)(Vb + ((nv << 3) + lr) * VPS + fo);
                    mma16(o_acc + 4 * nv, pa[j], bf.x, bf.y);
                }
            }
        }
    }

    // ---- epilogue: quad-reduce l, normalize, store ----
    l0 += __shfl_xor_sync(0xffffffffu, l0, 1);
    l0 += __shfl_xor_sync(0xffffffffu, l0, 2);
    l1 += __shfl_xor_sync(0xffffffffu, l1, 1);
    l1 += __shfl_xor_sync(0xffffffffu, l1, 2);
    const float i0 = 1.f / l0;
    const float i1 = 1.f / l1;

    float* o0 = out + (size_t)rg0 * 4096 + b * 2048 + h * 128;
    float* o1 = o0 + (size_t)8 * 4096;
#pragma unroll
    for (int nv = 0; nv < 16; ++nv) {
        const int c = (nv << 3) + (lc << 1);
        *(float2*)(o0 + c) = make_float2(o_acc[4 * nv + 0] * i0,
                                         o_acc[4 * nv + 1] * i0);
        *(float2*)(o1 + c) = make_float2(o_acc[4 * nv + 2] * i1,
                                         o_acc[4 * nv + 3] * i1);
    }
}

extern "C" void kernel_launch(void* const* d_in, const int* in_sizes, int n_in,
                              void* d_out, int out_size)
{
    const float* Q = (const float*)d_in[0];
    const float* K = (const float*)d_in[1];
    const float* V = (const float*)d_in[2];
    float* out = (float*)d_out;

    cudaFuncSetAttribute(fa_rp_kernel,
                         cudaFuncAttributeMaxDynamicSharedMemorySize, SMEM_BYTES);
    dim3 grid(16, 32);   // (q tiles of 128, b*h)
    fa_rp_kernel<<<grid, NT, SMEM_BYTES>>>(Q, K, V, out);
}

// round 14
// speedup vs baseline: 1.7973x; 1.7973x over previous
#include <cuda_runtime.h>
#include <cuda_fp16.h>
#include <cstdint>

// Flash-attention (causal), round 13: fp16 mma.sync + prepass-converted K/V
// tile images streamed via cp.async (3-stage pipeline).
// Main: 256 threads (8 warps), BM=128, BN=32, 2 CTAs/SM, warp-private P in regs.
// q/k/v: [2048, 2, 16, 128] fp32 sbhd.  out: [2048, 2, 2048] fp32.

#define SSTRIDE  4096
#define QSCALE   (0.08838834764831845f * 1.4426950408889634f)  // scale * log2(e)
#define NT       256
#define QKS      72                  // Q/K row stride in u32 words (smem)
#define VPS      24                  // V row stride in u32 words (smem)

#define Q_U32  (128 * QKS)           // 9216
#define KSTG   (32 * QKS)            // 2304
#define VSTG   (128 * VPS)           // 3072
#define STG    (KSTG + VSTG)         // 5376
#define SMEM_U32 (Q_U32 + 3 * STG)
#define SMEM_BYTES (SMEM_U32 * 4)    // 101376

// fp16 tile images: [32 bh][64 tiles][512 uint4]  (8KB per tile, pad-free)
static __device__ uint4 g_Kc[32 * 64 * 512];
static __device__ uint4 g_Vc[32 * 64 * 512];

__device__ __forceinline__ void mma16(float* d, const uint32_t* a,
                                      uint32_t b0, uint32_t b1) {
    asm("mma.sync.aligned.m16n8k16.row.col.f32.f16.f16.f32 "
        "{%0,%1,%2,%3}, {%4,%5,%6,%7}, {%8,%9}, {%0,%1,%2,%3};"
        : "+f"(d[0]), "+f"(d[1]), "+f"(d[2]), "+f"(d[3])
        : "r"(a[0]), "r"(a[1]), "r"(a[2]), "r"(a[3]), "r"(b0), "r"(b1));
}
__device__ __forceinline__ uint32_t pack2(float x, float y) {
    uint32_t r;
    asm("cvt.rn.f16x2.f32 %0, %2, %1;" : "=r"(r) : "f"(x), "f"(y));
    return r;
}
__device__ __forceinline__ uint32_t smem_u32(const void* p) {
    uint32_t a;
    asm("{ .reg .u64 t; cvta.to.shared.u64 t, %1; cvt.u32.u64 %0, t; }"
        : "=r"(a) : "l"(p));
    return a;
}
#define CP16(dst_b, src_p) \
    asm volatile("cp.async.cg.shared.global [%0], [%1], 16;" \
                 :: "r"(dst_b), "l"(src_p) : "memory")
#define CP_COMMIT() asm volatile("cp.async.commit_group;" ::: "memory")
#define CP_WAIT1()  asm volatile("cp.async.wait_group 1;" ::: "memory")

// ---------------- prepass: K -> fp16 interleaved image ----------------
__global__ __launch_bounds__(256)
void prep_k(const float* __restrict__ K)
{
    const int gid = blockIdx.x * 256 + threadIdx.x;   // 32*2048*16 threads
    const int j  = gid & 15;
    const int n  = (gid >> 4) & 2047;
    const int bh = gid >> 15;

    const float* src = K + (size_t)n * SSTRIDE + bh * 128 + (j << 3);
    float4 x = *(const float4*)(src);
    float4 y = *(const float4*)(src + 4);

    const int t = n >> 5, r = n & 31;
    const int woff = ((j >> 1) << 3) + (j & 1);
    uint32_t* dst = (uint32_t*)(g_Kc + (size_t)(bh * 64 + t) * 512)
                    + r * 64 + woff;
    dst[0] = pack2(x.x, x.y);
    dst[2] = pack2(x.z, x.w);
    dst[4] = pack2(y.x, y.y);
    dst[6] = pack2(y.z, y.w);
}

// ---------------- prepass: V -> fp16 d-row image ----------------
__global__ __launch_bounds__(256)
void prep_v(const float* __restrict__ V)
{
    const int gid = blockIdx.x * 256 + threadIdx.x;   // 32*1024*32 threads
    const int vdg = gid & 31;
    const int qpg = (gid >> 5) & 1023;
    const int bh  = gid >> 15;

    const float* src = V + (size_t)(2 * qpg) * SSTRIDE + bh * 128 + (vdg << 2);
    float4 a = *(const float4*)(src);
    float4 c = *(const float4*)(src + SSTRIDE);

    const int t   = qpg >> 4;
    const int qpl = qpg & 15;
    const int s   = qpl >> 3;
    const int v0  = qpl & 7;
    const int vw  = (s << 3) + ((v0 & 3) << 1) + (v0 >> 2);
    uint32_t* dst = (uint32_t*)(g_Vc + (size_t)(bh * 64 + t) * 512);
    const int d0 = vdg << 2;
    dst[(d0 + 0) * 16 + vw] = pack2(a.x, c.x);
    dst[(d0 + 1) * 16 + vw] = pack2(a.y, c.y);
    dst[(d0 + 2) * 16 + vw] = pack2(a.z, c.z);
    dst[(d0 + 3) * 16 + vw] = pack2(a.w, c.w);
}

// ---------------- main kernel ----------------
__global__ __launch_bounds__(NT, 2)
void fa_cp_kernel(const float* __restrict__ Q,
                  float* __restrict__ out)
{
    extern __shared__ uint32_t su[];
    uint32_t* Qh = su;                       // [128 rows][QKS]
    const uint32_t sbase = smem_u32(su);

    const int tid  = threadIdx.x;
    const int wid  = tid >> 5;
    const int lane = tid & 31;
    const int lr   = lane >> 2;
    const int lc   = lane & 3;

    const int qt = 15 - (int)blockIdx.x;     // heavy q-tiles first
    const int bh = (int)blockIdx.y;
    const int b  = bh >> 4;
    const int h  = bh & 15;
    const float* Qg = Q + bh * 128;
    const uint4* Ktiles = g_Kc + (size_t)bh * 64 * 512;
    const uint4* Vtiles = g_Vc + (size_t)bh * 64 * 512;

    const int q0       = qt * 128;
    const int wbase    = wid << 4;
    const int row_loc0 = wbase + lr;
    const int rg0      = q0 + row_loc0;
    const int rg1      = rg0 + 8;
    const int wrow_min = q0 + wbase;
    const int wrow_max = wrow_min + 15;

    // per-thread cp.async chunk coords (chunks c0 = tid, c1 = tid+256)
    const int c0 = tid, c1 = tid + 256;
    const uint32_t kdst0 = (uint32_t)((c0 >> 4) * QKS + (c0 & 15) * 4) * 4;
    const uint32_t kdst1 = (uint32_t)((c1 >> 4) * QKS + (c1 & 15) * 4) * 4;
    const uint32_t vdst0 = (uint32_t)((c0 >> 2) * VPS + (c0 & 3) * 4) * 4;
    const uint32_t vdst1 = (uint32_t)((c1 >> 2) * VPS + (c1 & 3) * 4) * 4;

#define ISSUE_TILE(tile, st) do {                                             \
    const uint32_t base = sbase + (uint32_t)(Q_U32 + (st) * STG) * 4;         \
    const uint4* kt_ = Ktiles + (size_t)(tile) * 512;                         \
    const uint4* vt_ = Vtiles + (size_t)(tile) * 512;                         \
    CP16(base + kdst0, kt_ + c0);                                             \
    CP16(base + kdst1, kt_ + c1);                                             \
    CP16(base + KSTG * 4 + vdst0, vt_ + c0);                                  \
    CP16(base + KSTG * 4 + vdst1, vt_ + c1);                                  \
} while (0)

    const int ktmax = 4 * qt + 3;

    // prologue: tiles 0 and 1 in flight
    ISSUE_TILE(0, 0); CP_COMMIT();
    ISSUE_TILE(1, 1); CP_COMMIT();

    // ---- Q tile -> Qh (fp16, pre-scaled by QSCALE) ----
    {
        const int j = tid & 15;
        const int woff = ((j >> 1) << 3) + (j & 1);
        const int r0 = tid >> 4;
#pragma unroll
        for (int s = 0; s < 8; ++s) {
            const int r = r0 + (s << 4);
            const float* src = Qg + (size_t)(q0 + r) * SSTRIDE + (j << 3);
            float4 x = *(const float4*)(src);
            float4 y = *(const float4*)(src + 4);
            uint32_t* d = Qh + r * QKS + woff;
            d[0] = pack2(x.x * QSCALE, x.y * QSCALE);
            d[2] = pack2(x.z * QSCALE, x.w * QSCALE);
            d[4] = pack2(y.x * QSCALE, y.y * QSCALE);
            d[6] = pack2(y.z * QSCALE, y.w * QSCALE);
        }
    }

    float o_acc[64];
#pragma unroll
    for (int i = 0; i < 64; ++i) o_acc[i] = 0.f;
    float l0 = 0.f, l1 = 0.f;

    int stc = 0;
    for (int kt = 0; kt <= ktmax; ++kt) {
        const int k0 = kt << 5;
        CP_WAIT1();            // tile kt landed (own chunks)
        __syncthreads();       // everyone's chunks + WAR on reissued stage

        const uint32_t* Kb = su + Q_U32 + stc * STG;
        const uint32_t* Vb = Kb + KSTG;

        const bool skip = (k0 > wrow_max);
        if (!skip) {
            // ---- MMA1: S[16,32] = Q x K^T (Q pre-scaled) ----
            float sc[16];
#pragma unroll
            for (int i = 0; i < 16; ++i) sc[i] = 0.f;
#pragma unroll
            for (int ks = 0; ks < 8; ++ks) {
                const int fo = (ks << 3) + (lc << 1);
                uint2 a02 = *(const uint2*)(Qh + row_loc0 * QKS + fo);
                uint2 a13 = *(const uint2*)(Qh + (row_loc0 + 8) * QKS + fo);
                uint32_t a[4] = { a02.x, a13.x, a02.y, a13.y };
#pragma unroll
                for (int nt = 0; nt < 4; ++nt) {
                    uint2 bf = *(const uint2*)(Kb + ((nt << 3) + lr) * QKS + fo);
                    mma16(sc + 4 * nt, a, bf.x, bf.y);
                }
            }

            // ---- softmax (unnormalized, 2^s) + pack P into A-frag regs ----
            const bool diag = (k0 + 31 > wrow_min);
            uint32_t pa[2][4];
#pragma unroll
            for (int nt = 0; nt < 4; ++nt) {
                const int cg = k0 + (nt << 3) + (lc << 1);
                float p00 = exp2f(sc[4 * nt + 0]);
                float p01 = exp2f(sc[4 * nt + 1]);
                float p10 = exp2f(sc[4 * nt + 2]);
                float p11 = exp2f(sc[4 * nt + 3]);
                if (diag) {
                    if (cg     > rg0) p00 = 0.f;
                    if (cg + 1 > rg0) p01 = 0.f;
                    if (cg     > rg1) p10 = 0.f;
                    if (cg + 1 > rg1) p11 = 0.f;
                }
                l0 += p00 + p01;
                l1 += p10 + p11;
                pa[nt >> 1][((nt & 1) << 1) + 0] = pack2(p00, p01);
                pa[nt >> 1][((nt & 1) << 1) + 1] = pack2(p10, p11);
            }

            // ---- MMA2: O[16,128] += P[16,32] x V[32,128] ----
#pragma unroll
            for (int j = 0; j < 2; ++j) {
                const int fo = (j << 3) + (lc << 1);
#pragma unroll
                for (int nv = 0; nv < 16; ++nv) {
                    uint2 bf = *(const uint2*)(Vb + ((nv << 3) + lr) * VPS + fo);
                    mma16(o_acc + 4 * nv, pa[j], bf.x, bf.y);
                }
            }
        }

        // ---- issue tile kt+2 into stage (kt+2)%3; commit ALWAYS ----
        if (kt + 2 <= ktmax) {
            int sti = stc + 2; if (sti >= 3) sti -= 3;
            ISSUE_TILE(kt + 2, sti);
        }
        CP_COMMIT();
        if (++stc == 3) stc = 0;
    }

    // ---- epilogue: quad-reduce l, normalize, store ----
    l0 += __shfl_xor_sync(0xffffffffu, l0, 1);
    l0 += __shfl_xor_sync(0xffffffffu, l0, 2);
    l1 += __shfl_xor_sync(0xffffffffu, l1, 1);
    l1 += __shfl_xor_sync(0xffffffffu, l1, 2);
    const float i0 = 1.f / l0;
    const float i1 = 1.f / l1;

    float* o0 = out + (size_t)rg0 * 4096 + b * 2048 + h * 128;
    float* o1 = o0 + (size_t)8 * 4096;
#pragma unroll
    for (int nv = 0; nv < 16; ++nv) {
        const int c = (nv << 3) + (lc << 1);
        *(float2*)(o0 + c) = make_float2(o_acc[4 * nv + 0] * i0,
                                         o_acc[4 * nv + 1] * i0);
        *(float2*)(o1 + c) = make_float2(o_acc[4 * nv + 2] * i1,
                                         o_acc[4 * nv + 3] * i1);
    }
}

extern "C" void kernel_launch(void* const* d_in, const int* in_sizes, int n_in,
                              void* d_out, int out_size)
{
    const float* Q = (const float*)d_in[0];
    const float* K = (const float*)d_in[1];
    const float* V = (const float*)d_in[2];
    float* out = (float*)d_out;

    prep_k<<<4096, 256>>>(K);
    prep_v<<<4096, 256>>>(V);

    cudaFuncSetAttribute(fa_cp_kernel,
                         cudaFuncAttributeMaxDynamicSharedMemorySize, SMEM_BYTES);
    dim3 grid(16, 32);   // (q tiles of 128, b*h)
    fa_cp_kernel<<<grid, NT, SMEM_BYTES>>>(Q, out);
}

// round 15
// speedup vs baseline: 1.9061x; 1.0605x over previous
#include <cuda_runtime.h>
#include <cuda_fp16.h>
#include <cstdint>

// Flash-attention (causal), round 15: fp16 mma.sync, prepass K/V images with
// coalesced stores, cp.async 3-stage pipeline, Q fragments register-resident.
// Main: 256 threads (8 warps), BM=128, BN=32, 2 CTAs/SM.
// q/k/v: [2048, 2, 16, 128] fp32 sbhd.  out: [2048, 2, 2048] fp32.

#define SSTRIDE  4096
#define QSCALE   (0.08838834764831845f * 1.4426950408889634f)  // scale * log2(e)
#define NT       256
#define QKS      72                  // Q/K row stride in u32 words (smem)
#define VPS      24                  // V row stride in u32 words (smem)

#define Q_U32  (128 * QKS)           // 9216
#define KSTG   (32 * QKS)            // 2304
#define VSTG   (128 * VPS)           // 3072
#define STG    (KSTG + VSTG)         // 5376
#define SMEM_U32 (Q_U32 + 3 * STG)
#define SMEM_BYTES (SMEM_U32 * 4)    // 101376

// fp16 tile images: [32 bh][64 tiles][512 uint4]  (8KB per tile)
static __device__ uint4 g_Kc[32 * 64 * 512];
static __device__ uint4 g_Vc[32 * 64 * 512];

__device__ __forceinline__ void mma16(float* d, const uint32_t* a,
                                      uint32_t b0, uint32_t b1) {
    asm("mma.sync.aligned.m16n8k16.row.col.f32.f16.f16.f32 "
        "{%0,%1,%2,%3}, {%4,%5,%6,%7}, {%8,%9}, {%0,%1,%2,%3};"
        : "+f"(d[0]), "+f"(d[1]), "+f"(d[2]), "+f"(d[3])
        : "r"(a[0]), "r"(a[1]), "r"(a[2]), "r"(a[3]), "r"(b0), "r"(b1));
}
__device__ __forceinline__ uint32_t pack2(float x, float y) {
    uint32_t r;
    asm("cvt.rn.f16x2.f32 %0, %2, %1;" : "=r"(r) : "f"(x), "f"(y));
    return r;
}
__device__ __forceinline__ uint32_t smem_u32(const void* p) {
    uint32_t a;
    asm("{ .reg .u64 t; cvta.to.shared.u64 t, %1; cvt.u32.u64 %0, t; }"
        : "=r"(a) : "l"(p));
    return a;
}
#define CP16(dst_b, src_p) \
    asm volatile("cp.async.cg.shared.global [%0], [%1], 16;" \
                 :: "r"(dst_b), "l"(src_p) : "memory")
#define CP_COMMIT() asm volatile("cp.async.commit_group;" ::: "memory")
#define CP_WAIT1()  asm volatile("cp.async.wait_group 1;" ::: "memory")

// ---------------- prepass: K -> fp16 interleaved image (coalesced) ----------
// image word w (0..63) of row r: j = 2*(w>>3)+(w&1), u = (w>>1)&3,
// holds pack2(K[r][8j+2u], K[r][8j+2u+1]).
__global__ __launch_bounds__(256)
void prep_k(const float* __restrict__ K)
{
    const int wq = threadIdx.x & 15;                       // uint4 within row
    const int r  = ((blockIdx.x & 1) << 4) + (threadIdx.x >> 4);  // 0..31
    const int bt = blockIdx.x >> 1;                        // bh*64 + t
    const int bh = bt >> 6;
    const int t  = bt & 63;
    const int n  = (t << 5) + r;

    const float* row = K + (size_t)n * SSTRIDE + bh * 128;
    uint32_t wds[4];
#pragma unroll
    for (int m = 0; m < 4; ++m) {
        const int w = (wq << 2) + m;
        const int j = ((w >> 3) << 1) + (w & 1);
        const int u = (w >> 1) & 3;
        const float2 e = *(const float2*)(row + (j << 3) + (u << 1));
        wds[m] = pack2(e.x, e.y);
    }
    uint4* dst = (uint4*)((uint32_t*)(g_Kc + (size_t)bt * 512) + (r << 6)) + wq;
    *dst = make_uint4(wds[0], wds[1], wds[2], wds[3]);
}

// ---------------- prepass: V -> fp16 d-row image (coalesced) ----------------
// image word w (0..15) of d-row d: qp = 4*(w&1) + ((w>>1)&3) + 8*(w>>3),
// holds pack2(V[32t+2qp][d], V[32t+2qp+1][d]).
__global__ __launch_bounds__(256)
void prep_v(const float* __restrict__ V)
{
    const int wq  = threadIdx.x & 3;                       // uint4 within row
    const int dl  = (threadIdx.x >> 2) & 7;
    const int dh  = threadIdx.x >> 5;                      // 0..7
    const int bt  = blockIdx.x >> 1;
    const int bh  = bt >> 6;
    const int t   = bt & 63;
    const int d   = ((blockIdx.x & 1) << 6) + (dh << 3) + dl;   // 0..127

    const float* base = V + bh * 128 + d;
    uint32_t wds[4];
#pragma unroll
    for (int m = 0; m < 4; ++m) {
        const int w  = (wq << 2) + m;
        const int qp = ((w & 1) << 2) + ((w >> 1) & 3) + ((w >> 3) << 3);
        const int n  = (t << 5) + (qp << 1);
        const float a = base[(size_t)n * SSTRIDE];
        const float c = base[(size_t)(n + 1) * SSTRIDE];
        wds[m] = pack2(a, c);
    }
    uint4* dst = (uint4*)((uint32_t*)(g_Vc + (size_t)bt * 512) + (d << 4)) + wq;
    *dst = make_uint4(wds[0], wds[1], wds[2], wds[3]);
}

// ---------------- main kernel ----------------
__global__ __launch_bounds__(NT, 2)
void fa_cp_kernel(const float* __restrict__ Q,
                  float* __restrict__ out)
{
    extern __shared__ uint32_t su[];
    uint32_t* Qh = su;                       // [128 rows][QKS]
    const uint32_t sbase = smem_u32(su);

    const int tid  = threadIdx.x;
    const int wid  = tid >> 5;
    const int lane = tid & 31;
    const int lr   = lane >> 2;
    const int lc   = lane & 3;

    const int qt = 15 - (int)blockIdx.x;     // heavy q-tiles first
    const int bh = (int)blockIdx.y;
    const int b  = bh >> 4;
    const int h  = bh & 15;
    const float* Qg = Q + bh * 128;
    const uint4* Ktiles = g_Kc + (size_t)bh * 64 * 512;
    const uint4* Vtiles = g_Vc + (size_t)bh * 64 * 512;

    const int q0       = qt * 128;
    const int wbase    = wid << 4;
    const int row_loc0 = wbase + lr;
    const int rg0      = q0 + row_loc0;
    const int rg1      = rg0 + 8;
    const int wrow_min = q0 + wbase;
    const int wrow_max = wrow_min + 15;

    // per-thread cp.async chunk coords (chunks c0 = tid, c1 = tid+256)
    const int c0 = tid, c1 = tid + 256;
    const uint32_t kdst0 = (uint32_t)((c0 >> 4) * QKS + (c0 & 15) * 4) * 4;
    const uint32_t kdst1 = (uint32_t)((c1 >> 4) * QKS + (c1 & 15) * 4) * 4;
    const uint32_t vdst0 = (uint32_t)((c0 >> 2) * VPS + (c0 & 3) * 4) * 4;
    const uint32_t vdst1 = (uint32_t)((c1 >> 2) * VPS + (c1 & 3) * 4) * 4;

#define ISSUE_TILE(tile, st) do {                                             \
    const uint32_t base = sbase + (uint32_t)(Q_U32 + (st) * STG) * 4;         \
    const uint4* kt_ = Ktiles + (size_t)(tile) * 512;                         \
    const uint4* vt_ = Vtiles + (size_t)(tile) * 512;                         \
    CP16(base + kdst0, kt_ + c0);                                             \
    CP16(base + kdst1, kt_ + c1);                                             \
    CP16(base + KSTG * 4 + vdst0, vt_ + c0);                                  \
    CP16(base + KSTG * 4 + vdst1, vt_ + c1);                                  \
} while (0)

    const int ktmax = 4 * qt + 3;

    // prologue: tiles 0 and 1 in flight
    ISSUE_TILE(0, 0); CP_COMMIT();
    ISSUE_TILE(1, 1); CP_COMMIT();

    // ---- Q tile -> Qh (fp16, pre-scaled by QSCALE) ----
    {
        const int j = tid & 15;
        const int woff = ((j >> 1) << 3) + (j & 1);
        const int r0 = tid >> 4;
#pragma unroll
        for (int s = 0; s < 8; ++s) {
            const int r = r0 + (s << 4);
            const float* src = Qg + (size_t)(q0 + r) * SSTRIDE + (j << 3);
            float4 x = *(const float4*)(src);
            float4 y = *(const float4*)(src + 4);
            uint32_t* d = Qh + r * QKS + woff;
            d[0] = pack2(x.x * QSCALE, x.y * QSCALE);
            d[2] = pack2(x.z * QSCALE, x.w * QSCALE);
            d[4] = pack2(y.x * QSCALE, y.y * QSCALE);
            d[6] = pack2(y.z * QSCALE, y.w * QSCALE);
        }
    }
    __syncthreads();

    // ---- lift Q fragments into registers (Qh never read again) ----
    uint32_t qf[8][4];
#pragma unroll
    for (int ks = 0; ks < 8; ++ks) {
        const int fo = (ks << 3) + (lc << 1);
        uint2 a02 = *(const uint2*)(Qh + row_loc0 * QKS + fo);
        uint2 a13 = *(const uint2*)(Qh + (row_loc0 + 8) * QKS + fo);
        qf[ks][0] = a02.x; qf[ks][1] = a13.x;
        qf[ks][2] = a02.y; qf[ks][3] = a13.y;
    }

    float o_acc[64];
#pragma unroll
    for (int i = 0; i < 64; ++i) o_acc[i] = 0.f;
    float l0 = 0.f, l1 = 0.f;

    int stc = 0;
    for (int kt = 0; kt <= ktmax; ++kt) {
        const int k0 = kt << 5;
        CP_WAIT1();            // tile kt landed (own chunks)
        __syncthreads();       // everyone's chunks + WAR on reissued stage

        const uint32_t* Kb = su + Q_U32 + stc * STG;
        const uint32_t* Vb = Kb + KSTG;

        const bool skip = (k0 > wrow_max);
        if (!skip) {
            // ---- MMA1: S[16,32] = Q x K^T (Q pre-scaled, from regs) ----
            float sc[16];
#pragma unroll
            for (int i = 0; i < 16; ++i) sc[i] = 0.f;
#pragma unroll
            for (int ks = 0; ks < 8; ++ks) {
                const int fo = (ks << 3) + (lc << 1);
#pragma unroll
                for (int nt = 0; nt < 4; ++nt) {
                    uint2 bf = *(const uint2*)(Kb + ((nt << 3) + lr) * QKS + fo);
                    mma16(sc + 4 * nt, qf[ks], bf.x, bf.y);
                }
            }

            // ---- softmax (unnormalized, 2^s) + pack P into A-frag regs ----
            const bool diag = (k0 + 31 > wrow_min);
            uint32_t pa[2][4];
#pragma unroll
            for (int nt = 0; nt < 4; ++nt) {
                const int cg = k0 + (nt << 3) + (lc << 1);
                float p00 = exp2f(sc[4 * nt + 0]);
                float p01 = exp2f(sc[4 * nt + 1]);
                float p10 = exp2f(sc[4 * nt + 2]);
                float p11 = exp2f(sc[4 * nt + 3]);
                if (diag) {
                    if (cg     > rg0) p00 = 0.f;
                    if (cg + 1 > rg0) p01 = 0.f;
                    if (cg     > rg1) p10 = 0.f;
                    if (cg + 1 > rg1) p11 = 0.f;
                }
                l0 += p00 + p01;
                l1 += p10 + p11;
                pa[nt >> 1][((nt & 1) << 1) + 0] = pack2(p00, p01);
                pa[nt >> 1][((nt & 1) << 1) + 1] = pack2(p10, p11);
            }

            // ---- MMA2: O[16,128] += P[16,32] x V[32,128] ----
#pragma unroll
            for (int j = 0; j < 2; ++j) {
                const int fo = (j << 3) + (lc << 1);
#pragma unroll
                for (int nv = 0; nv < 16; ++nv) {
                    uint2 bf = *(const uint2*)(Vb + ((nv << 3) + lr) * VPS + fo);
                    mma16(o_acc + 4 * nv, pa[j], bf.x, bf.y);
                }
            }
        }

        // ---- issue tile kt+2 into stage (kt+2)%3; commit ALWAYS ----
        if (kt + 2 <= ktmax) {
            int sti = stc + 2; if (sti >= 3) sti -= 3;
            ISSUE_TILE(kt + 2, sti);
        }
        CP_COMMIT();
        if (++stc == 3) stc = 0;
    }

    // ---- epilogue: quad-reduce l, normalize, store ----
    l0 += __shfl_xor_sync(0xffffffffu, l0, 1);
    l0 += __shfl_xor_sync(0xffffffffu, l0, 2);
    l1 += __shfl_xor_sync(0xffffffffu, l1, 1);
    l1 += __shfl_xor_sync(0xffffffffu, l1, 2);
    const float i0 = 1.f / l0;
    const float i1 = 1.f / l1;

    float* o0 = out + (size_t)rg0 * 4096 + b * 2048 + h * 128;
    float* o1 = o0 + (size_t)8 * 4096;
#pragma unroll
    for (int nv = 0; nv < 16; ++nv) {
        const int c = (nv << 3) + (lc << 1);
        *(float2*)(o0 + c) = make_float2(o_acc[4 * nv + 0] * i0,
                                         o_acc[4 * nv + 1] * i0);
        *(float2*)(o1 + c) = make_float2(o_acc[4 * nv + 2] * i1,
                                         o_acc[4 * nv + 3] * i1);
    }
}

extern "C" void kernel_launch(void* const* d_in, const int* in_sizes, int n_in,
                              void* d_out, int out_size)
{
    const float* Q = (const float*)d_in[0];
    const float* K = (const float*)d_in[1];
    const float* V = (const float*)d_in[2];
    float* out = (float*)d_out;

    prep_k<<<4096, 256>>>(K);
    prep_v<<<4096, 256>>>(V);

    cudaFuncSetAttribute(fa_cp_kernel,
                         cudaFuncAttributeMaxDynamicSharedMemorySize, SMEM_BYTES);
    dim3 grid(16, 32);   // (q tiles of 128, b*h)
    fa_cp_kernel<<<grid, NT, SMEM_BYTES>>>(Q, out);
}